// round 13
// baseline (speedup 1.0000x reference)
#include <cuda_runtime.h>
#include <cstdint>

#define NB 2
#define CIN 1024
#define HH 50
#define WW 50
#define SPAT 2500
#define SATN 51
#define SATSP (SATN * SATN)
#define RR 300
#define PQN 49
#define NCLS 21
#define ROWS_CLS 1029
#define ROWS_TOT 1225
#define COMB 25

// ---------------- scratch (static device memory; no allocations) ----------------
__device__ float4 g_ht4[(size_t)NB * SPAT * (CIN / 4)];   // tf32(h) channel-last
__device__ float4 g_sat4[(size_t)NB * SATSP * (CIN / 4)]; // SAT
__device__ float4 g_A4[(size_t)ROWS_TOT * (CIN / 4)];     // tf32(wc‖wl)
__device__ float4 g_B4[(size_t)CIN * (CIN / 4)];          // tf32(w1)
__device__ float4 g_W4[(size_t)ROWS_TOT * (CIN / 4)];     // folded weights (tf32 values)
__device__ float  g_bias[ROWS_TOT];                       // folded bias
__device__ float  g_scr[(size_t)RR * COMB * PQN];         // per-(roi,c,pq) values

// fp32 -> tf32-rounded fp32
__device__ __forceinline__ float tf32r(float x) {
  unsigned u;
  asm("cvt.rna.tf32.f32 %0, %1;" : "=r"(u) : "f"(x));
  return __uint_as_float(u);
}
__device__ __forceinline__ float4 tf32r4(float4 v) {
  return make_float4(tf32r(v.x), tf32r(v.y), tf32r(v.z), tf32r(v.w));
}

// cp.async helpers
__device__ __forceinline__ void cpa16(void* smem, const void* gmem, int srcsz) {
  uint32_t s = (uint32_t)__cvta_generic_to_shared(smem);
  asm volatile("cp.async.cg.shared.global [%0], [%1], 16, %2;\n"
               :: "r"(s), "l"(gmem), "r"(srcsz));
}
#define CP_COMMIT() asm volatile("cp.async.commit_group;\n" ::: "memory")
#define CP_WAIT1()  asm volatile("cp.async.wait_group 1;\n" ::: "memory")

// ---------------- K1: prep ∪ transpose ∪ bias (independent; blockIdx dispatch) -----
#define K1_PREP   (ROWS_TOT + CIN)                 // 2249 blocks
#define K1_TRX    ((79) * (CIN / 32) * NB)         // 79*32*2 = 5056 blocks
#define K1_BIAS   ((ROWS_TOT * 32 + 255) / 256)    // 154 blocks
__global__ __launch_bounds__(256) void k1_prep_trx_bias(
    const float* __restrict__ h,
    const float* __restrict__ w1, const float* __restrict__ b1,
    const float* __restrict__ wc, const float* __restrict__ bc,
    const float* __restrict__ wl, const float* __restrict__ bl) {
  __shared__ float tile[32][33];
  int bid = blockIdx.x;
  int t = threadIdx.x;

  if (bid < K1_PREP) {               // ---- prep: tf32-round + concat weights
    int j = bid;
    if (j < ROWS_TOT) {
      const float4* src = (j < ROWS_CLS)
          ? (const float4*)(wc + (size_t)j * CIN)
          : (const float4*)(wl + (size_t)(j - ROWS_CLS) * CIN);
      g_A4[(size_t)j * 256 + t] = tf32r4(src[t]);
    } else {
      int r = j - ROWS_TOT;
      g_B4[(size_t)r * 256 + t] = tf32r4(((const float4*)(w1 + (size_t)r * CIN))[t]);
    }
  } else if (bid < K1_PREP + K1_TRX) { // ---- transpose h -> ht (tf32)
    int b = bid - K1_PREP;
    int sxb = b % 79; b /= 79;
    int c0b = b % (CIN / 32); int n = b / (CIN / 32);
    int s0 = sxb * 32, c0 = c0b * 32;
    int tx = t & 31, ty = t >> 5;
    float* ht = (float*)g_ht4;
#pragma unroll
    for (int i = 0; i < 32; i += 8) {
      int c = c0 + ty + i, s = s0 + tx;
      if (c < CIN && s < SPAT) tile[ty + i][tx] = h[((size_t)n * CIN + c) * SPAT + s];
    }
    __syncthreads();
#pragma unroll
    for (int i = 0; i < 32; i += 8) {
      int s = s0 + ty + i, c = c0 + tx;
      if (s < SPAT && c < CIN) ht[((size_t)n * SPAT + s) * CIN + c] = tf32r(tile[tx][ty + i]);
    }
  } else {                            // ---- folded bias
    int b = bid - K1_PREP - K1_TRX;
    int gw = (b * 256 + t) >> 5;
    int lane = t & 31;
    if (gw >= ROWS_TOT) return;
    const float* row = (gw < ROWS_CLS) ? (wc + (size_t)gw * CIN)
                                       : (wl + (size_t)(gw - ROWS_CLS) * CIN);
    float s = 0.f;
    for (int o = lane; o < CIN; o += 32) s += row[o] * b1[o];
#pragma unroll
    for (int off = 16; off; off >>= 1) s += __shfl_xor_sync(0xffffffffu, s, off);
    if (lane == 0) {
      float base = (gw < ROWS_CLS) ? bc[gw] : bl[gw - ROWS_CLS];
      g_bias[gw] = base + s;
    }
  }
}

// ---------------- K2: fold ∪ sat1 (both depend only on K1) ----------------
#define KT 16
#define NKT (CIN / KT)
#define APAD 20
#define BPAD 68
#define K2_FOLD (16 * 20)   // 320 blocks
#define K2_SAT1 (SATN * NB * 2)  // 204 blocks
__global__ __launch_bounds__(128) void k2_fold_sat1(int dummy) {
  __shared__ float As[3][64][APAD];
  __shared__ float Bs[3][KT][BPAD];
  int bid = blockIdx.x;
  int t = threadIdx.x;

  if (bid < K2_FOLD) {   // ---- fold GEMM (identical to R12 k_fold_mma)
    int warp = t >> 5, lane = t & 31;
    int n0 = (bid % 16) * 64;
    int m0 = (bid / 16) * 64;
    int warpM = warp >> 1, warpN = warp & 1;
    int mb = warpM * 32, nb = warpN * 32;
    int lg = lane >> 2, lt = lane & 3;

    const float* A = (const float*)g_A4;
    const float* B = (const float*)g_B4;

    int a_row0 = t >> 2, a_kq0 = (t & 3) << 2;
    int a_row1 = (128 + t) >> 2, a_kq1 = ((128 + t) & 3) << 2;
    int gm0 = m0 + a_row0, gm1 = m0 + a_row1;
    int ok0 = (gm0 < ROWS_TOT) ? 16 : 0;
    int ok1 = (gm1 < ROWS_TOT) ? 16 : 0;
    const float* a_src0 = A + (size_t)(ok0 ? gm0 : 0) * CIN + a_kq0;
    const float* a_src1 = A + (size_t)(ok1 ? gm1 : 0) * CIN + a_kq1;

    float c0[2][4], c1[2][4], c2[2][4], c3[2][4];
#pragma unroll
    for (int i = 0; i < 2; i++)
#pragma unroll
      for (int j = 0; j < 4; j++) { c0[i][j] = c1[i][j] = c2[i][j] = c3[i][j] = 0.f; }

    auto load_tile = [&](int kt, int st) {
      int k0 = kt * KT;
      cpa16(&As[st][a_row0][a_kq0], a_src0 + k0, ok0);
      cpa16(&As[st][a_row1][a_kq1], a_src1 + k0, ok1);
#pragma unroll
      for (int i = 0; i < 2; i++) {
        int idx = i * 128 + t;
        int kr = idx >> 4;
        int nq = (idx & 15) << 2;
        cpa16(&Bs[st][kr][nq], B + (size_t)(k0 + kr) * CIN + n0 + nq, 16);
      }
    };

    load_tile(0, 0); CP_COMMIT();
    load_tile(1, 1); CP_COMMIT();

    for (int kt = 0; kt < NKT; kt++) {
      int st = kt % 3;
      CP_WAIT1();
      __syncthreads();
#pragma unroll
      for (int ks = 0; ks < 2; ks++) {
        int kc = ks << 3;
        uint32_t a[2][4];
#pragma unroll
        for (int ms = 0; ms < 2; ms++) {
          int row = mb + (ms << 4) + lg;
          a[ms][0] = __float_as_uint(As[st][row][kc + lt]);
          a[ms][1] = __float_as_uint(As[st][row + 8][kc + lt]);
          a[ms][2] = __float_as_uint(As[st][row][kc + 4 + lt]);
          a[ms][3] = __float_as_uint(As[st][row + 8][kc + 4 + lt]);
        }
        uint32_t b[4][2];
#pragma unroll
        for (int ns = 0; ns < 4; ns++) {
          int col = nb + (ns << 3) + lg;
          b[ns][0] = __float_as_uint(Bs[st][kc + lt][col]);
          b[ns][1] = __float_as_uint(Bs[st][kc + 4 + lt][col]);
        }
#pragma unroll
        for (int ms = 0; ms < 2; ms++)
#pragma unroll
          for (int ns = 0; ns < 4; ns++) {
            asm volatile(
              "mma.sync.aligned.m16n8k8.row.col.f32.tf32.tf32.f32 "
              "{%0,%1,%2,%3}, {%4,%5,%6,%7}, {%8,%9}, {%0,%1,%2,%3};"
              : "+f"(c0[ms][ns]), "+f"(c1[ms][ns]), "+f"(c2[ms][ns]), "+f"(c3[ms][ns])
              : "r"(a[ms][0]), "r"(a[ms][1]), "r"(a[ms][2]), "r"(a[ms][3]),
                "r"(b[ns][0]), "r"(b[ns][1]));
          }
      }
      if (kt + 2 < NKT) load_tile(kt + 2, (kt + 2) % 3);
      CP_COMMIT();
    }

    float* W = (float*)g_W4;
#pragma unroll
    for (int ms = 0; ms < 2; ms++) {
      int gr = m0 + mb + (ms << 4) + lg;
#pragma unroll
      for (int ns = 0; ns < 4; ns++) {
        int gc = n0 + nb + (ns << 3) + (lt << 1);
        if (gr < ROWS_TOT)
          *(float2*)(W + (size_t)gr * CIN + gc) =
              make_float2(tf32r(c0[ms][ns]), tf32r(c1[ms][ns]));
        if (gr + 8 < ROWS_TOT)
          *(float2*)(W + (size_t)(gr + 8) * CIN + gc) =
              make_float2(tf32r(c2[ms][ns]), tf32r(c3[ms][ns]));
      }
    }
  } else {              // ---- sat1: prefix along x (8-deep prefetch)
    int b = bid - K2_FOLD;
    int by = b % SATN; b /= SATN;
    int n = b & 1;
    int c4 = (b >> 1) * 128 + t;
    float4* satb = g_sat4 + (size_t)n * SATSP * 256;
    if (by == 0) {
      float4 z = make_float4(0.f, 0.f, 0.f, 0.f);
      for (int x = 0; x < SATN; x++) satb[(size_t)x * 256 + c4] = z;
      return;
    }
    int y = by - 1;
    const float4* src = g_ht4 + ((size_t)n * SPAT + y * WW) * 256 + c4;
    float4* dst = satb + (size_t)(by * SATN) * 256 + c4;
    float4 acc = make_float4(0.f, 0.f, 0.f, 0.f);
    dst[0] = acc;
    float4 buf[8];
#pragma unroll
    for (int i = 0; i < 8; i++) buf[i] = src[(size_t)i * 256];
    for (int x0 = 0; x0 < 48; x0 += 8) {
#pragma unroll
      for (int j = 0; j < 8; j++) {
        float4 v = buf[j];
        if (x0 + 8 + j < WW) buf[j] = src[(size_t)(x0 + 8 + j) * 256];
        acc.x += v.x; acc.y += v.y; acc.z += v.z; acc.w += v.w;
        dst[(size_t)(x0 + 1 + j) * 256] = acc;
      }
    }
#pragma unroll
    for (int j = 0; j < 2; j++) {
      float4 v = buf[j];
      acc.x += v.x; acc.y += v.y; acc.z += v.z; acc.w += v.w;
      dst[(size_t)(49 + j) * 256] = acc;
    }
  }
}

// ---------------- K3: sat2 (prefix along y, in place, 8-deep prefetch) --------------
__global__ __launch_bounds__(128) void k_sat2() {
  int x = blockIdx.x;
  int n = blockIdx.y;
  int c4 = blockIdx.z * 128 + threadIdx.x;
  float4* p = g_sat4 + ((size_t)n * SATSP + x) * 256 + c4;
  const size_t RS = (size_t)SATN * 256;
  float4 acc = make_float4(0.f, 0.f, 0.f, 0.f);
  float4 buf[8];
#pragma unroll
  for (int i = 0; i < 8; i++) buf[i] = p[(size_t)(1 + i) * RS];
  for (int y0 = 0; y0 < 48; y0 += 8) {
#pragma unroll
    for (int j = 0; j < 8; j++) {
      float4 v = buf[j];
      if (y0 + 9 + j <= 50) buf[j] = p[(size_t)(y0 + 9 + j) * RS];
      acc.x += v.x; acc.y += v.y; acc.z += v.z; acc.w += v.w;
      p[(size_t)(y0 + 1 + j) * RS] = acc;
    }
  }
#pragma unroll
  for (int j = 0; j < 2; j++) {
    float4 v = buf[j];
    acc.x += v.x; acc.y += v.y; acc.z += v.z; acc.w += v.w;
    p[(size_t)(49 + j) * RS] = acc;
  }
}

// ---------------- roi geometry: XLA semantics (byte-identical to passing rounds) ----
__device__ __forceinline__ void roi_geom(const float* __restrict__ rois, int r, int p, int q,
                                         int& hs, int& he, int& ws, int& we) {
  float x1 = rois[4 * r + 0], y1 = rois[4 * r + 1];
  float x2 = rois[4 * r + 2], y2 = rois[4 * r + 3];
  float sw = __fmul_rn(rintf(x1), 0.0625f);
  float sh = __fmul_rn(rintf(y1), 0.0625f);
  float ew = __fmul_rn(rintf(__fadd_rn(x2, 1.0f)), 0.0625f);
  float eh = __fmul_rn(rintf(__fadd_rn(y2, 1.0f)), 0.0625f);
  float rw = fmaxf(__fadd_rn(ew, -sw), 0.1f);
  float rh = fmaxf(__fadd_rn(eh, -sh), 0.1f);
  const float RSEV = 1.0f / 7.0f;   // XLA: /7 -> * fl(1/7)
  float bh = __fmul_rn(rh, RSEV);
  float bw = __fmul_rn(rw, RSEV);
  float fp = (float)p, fq = (float)q;
  hs = (int)fminf(fmaxf(floorf(__fadd_rn(__fmul_rn(fp, bh), sh)), 0.f), 50.f);
  he = (int)fminf(fmaxf(ceilf(__fadd_rn(__fmul_rn(__fadd_rn(fp, 1.f), bh), sh)), 0.f), 50.f);
  ws = (int)fminf(fmaxf(floorf(__fadd_rn(__fmul_rn(fq, bw), sw)), 0.f), 50.f);
  we = (int)fminf(fmaxf(ceilf(__fadd_rn(__fmul_rn(__fadd_rn(fq, 1.f), bw), sw)), 0.f), 50.f);
}

__device__ __forceinline__ int row_of(int c, int pq) {
  return (c < NCLS) ? (c * PQN + pq) : (ROWS_CLS + (c - NCLS) * PQN + pq);
}

// ---------------- K4: fused pool + projection ----------------
// Phase A: cp.async corner staging (2-stage, 16KB each); Phase B as R12.
#define CHUNK 16
#define PSTR 1028
#define STG_F (4 * 1024)          // floats per stage (4 corners x 1024)
__global__ __launch_bounds__(128) void k_poolproj(const float* __restrict__ rois,
                                                  const int* __restrict__ ridx) {
  extern __shared__ float smem[];
  float* Ps = smem;                              // [CHUNK][PSTR]
  float* Stg = smem + CHUNK * PSTR;              // [2][4][1024]
  __shared__ float As2[2][32][68];
  __shared__ float biasS[32];
  __shared__ float maskS[CHUNK];
  int pq = blockIdx.x, g = blockIdx.y;
  int p = pq / 7, q = pq - p * 7;
  int t = threadIdx.x;
  int warp = t >> 5, lane = t & 31;
  int lg = lane >> 2, lt = lane & 3;

  if (t < 32) biasS[t] = (t < COMB) ? g_bias[row_of(t, pq)] : 0.f;

  const float* satf = (const float*)g_sat4;

  // issue corner loads for roi rr into stage st
  auto stage_load = [&](int rr, int st) {
    int r = g * CHUNK + rr;
    float* sdst = Stg + st * STG_F;
    if (r < RR) {
      int hs, he, ws, we;
      roi_geom(rois, r, p, q, hs, he, ws, we);
      int n = ridx[r];
      size_t base = (size_t)n * SATSP * 1024;
      size_t corner[4] = {
        base + (size_t)(he * SATN + we) * 1024,
        base + (size_t)(hs * SATN + we) * 1024,
        base + (size_t)(he * SATN + ws) * 1024,
        base + (size_t)(hs * SATN + ws) * 1024,
      };
#pragma unroll
      for (int c = 0; c < 4; c++) {
#pragma unroll
        for (int i = 0; i < 2; i++) {
          int f = (t * 2 + i) * 4;        // float offset within 1024
          cpa16(&sdst[c * 1024 + f], satf + corner[c] + f, 16);
        }
      }
    } else {
#pragma unroll
      for (int c = 0; c < 4; c++)
#pragma unroll
        for (int i = 0; i < 2; i++) {
          int f = (t * 2 + i) * 4;
          cpa16(&sdst[c * 1024 + f], satf, 0);   // zero-fill
        }
    }
  };

  stage_load(0, 0); CP_COMMIT();
  stage_load(1, 1); CP_COMMIT();

  for (int rr = 0; rr < CHUNK; rr++) {
    int st = rr & 1;
    CP_WAIT1();
    __syncthreads();
    // compute pooled vector for roi rr from staged corners
    int r = g * CHUNK + rr;
    float rcp = 0.f;
    int cnt = 0;
    if (r < RR) {
      int hs, he, ws, we;
      roi_geom(rois, r, p, q, hs, he, ws, we);
      cnt = (he - hs) * (we - ws);
      rcp = (cnt > 0) ? __fdiv_rn(1.0f, (float)cnt) : 0.0f;
    }
    const float* sc = Stg + st * STG_F;
#pragma unroll
    for (int sgm = 0; sgm < 2; sgm++) {
      int f = (t + sgm * 128) << 2;
      float4 s11 = *(const float4*)&sc[0 * 1024 + f];
      float4 s01 = *(const float4*)&sc[1 * 1024 + f];
      float4 s10 = *(const float4*)&sc[2 * 1024 + f];
      float4 s00 = *(const float4*)&sc[3 * 1024 + f];
      float4 acc = make_float4(((s11.x - s01.x) - (s10.x - s00.x)) * rcp,
                               ((s11.y - s01.y) - (s10.y - s00.y)) * rcp,
                               ((s11.z - s01.z) - (s10.z - s00.z)) * rcp,
                               ((s11.w - s01.w) - (s10.w - s00.w)) * rcp);
      *(float4*)&Ps[rr * PSTR + f] = tf32r4(acc);
    }
    if (t == 0) maskS[rr] = (r < RR && cnt > 0) ? 1.0f : 0.0f;
    __syncthreads();                       // stage reads done before re-fill
    if (rr + 2 < CHUNK) stage_load(rr + 2, st);
    CP_COMMIT();
  }

  // Phase B: S[m, roi] = W[row_of(m,pq), :] . P[roi, :]   (M=32, N=16, K=1024)
  int ms = warp >> 1, ns = warp & 1;
  float c0 = 0.f, c1 = 0.f, c2 = 0.f, c3 = 0.f;
  const float* W = (const float*)g_W4;

  int tr = t >> 4;
  int f4c = (t & 15) << 2;
  const float* wp[4];
  int wok[4];
#pragma unroll
  for (int i = 0; i < 4; i++) {
    int m = 8 * i + tr;
    wok[i] = (m < COMB);
    wp[i] = W + (size_t)row_of(wok[i] ? m : 0, pq) * CIN + f4c;
  }
  float4 wbuf[4];
#pragma unroll
  for (int i = 0; i < 4; i++)
    wbuf[i] = wok[i] ? *(const float4*)(wp[i]) : make_float4(0.f, 0.f, 0.f, 0.f);
#pragma unroll
  for (int i = 0; i < 4; i++) *(float4*)&As2[0][8 * i + tr][f4c] = wbuf[i];
  __syncthreads();

  for (int kt = 0; kt < 16; kt++) {
    if (kt < 15) {
      int koff = (kt + 1) << 6;
#pragma unroll
      for (int i = 0; i < 4; i++)
        wbuf[i] = wok[i] ? *(const float4*)(wp[i] + koff) : make_float4(0.f, 0.f, 0.f, 0.f);
    }
    int bufc = kt & 1;
    int kbase = kt << 6;
#pragma unroll
    for (int ks = 0; ks < 8; ks++) {
      int kc = ks << 3;
      int row = (ms << 4) + lg;
      uint32_t a0 = __float_as_uint(As2[bufc][row][kc + lt]);
      uint32_t a1 = __float_as_uint(As2[bufc][row + 8][kc + lt]);
      uint32_t a2 = __float_as_uint(As2[bufc][row][kc + 4 + lt]);
      uint32_t a3 = __float_as_uint(As2[bufc][row + 8][kc + 4 + lt]);
      int col = (ns << 3) + lg;
      uint32_t b0 = __float_as_uint(Ps[col * PSTR + kbase + kc + lt]);
      uint32_t b1 = __float_as_uint(Ps[col * PSTR + kbase + kc + 4 + lt]);
      asm volatile(
        "mma.sync.aligned.m16n8k8.row.col.f32.tf32.tf32.f32 "
        "{%0,%1,%2,%3}, {%4,%5,%6,%7}, {%8,%9}, {%0,%1,%2,%3};"
        : "+f"(c0), "+f"(c1), "+f"(c2), "+f"(c3)
        : "r"(a0), "r"(a1), "r"(a2), "r"(a3), "r"(b0), "r"(b1));
    }
    if (kt < 15) {
#pragma unroll
      for (int i = 0; i < 4; i++) *(float4*)&As2[1 - bufc][8 * i + tr][f4c] = wbuf[i];
      __syncthreads();
    }
  }

  // epilogue
  int m_lo = (ms << 4) + lg, m_hi = m_lo + 8;
  int col0 = (ns << 3) + (lt << 1);
  float b_lo = biasS[m_lo], b_hi = biasS[m_hi];
#pragma unroll
  for (int rr2 = 0; rr2 < 2; rr2++) {
    int col = col0 + rr2;
    int r = g * CHUNK + col;
    if (r < RR) {
      float mk = maskS[col];
      if (m_lo < COMB)
        g_scr[((size_t)r * COMB + m_lo) * PQN + pq] = ((rr2 ? c1 : c0) + b_lo) * mk;
      if (m_hi < COMB)
        g_scr[((size_t)r * COMB + m_hi) * PQN + pq] = ((rr2 ? c3 : c2) + b_hi) * mk;
    }
  }
}

// ---------------- K5: reduce: mean over 49 bins = sum * fl(1/49) ----------------
__global__ void k_reduce(float* __restrict__ out) {
  int idx = blockIdx.x * blockDim.x + threadIdx.x;
  if (idx >= RR * COMB) return;
  int r = idx / COMB, c = idx - r * COMB;
  const float* src = g_scr + (size_t)idx * PQN;
  float s = 0.f;
#pragma unroll
  for (int pq = 0; pq < PQN; pq++) s += src[pq];
  float mean = __fmul_rn(s, 1.0f / 49.0f);
  if (c < NCLS) out[r * NCLS + c] = mean;                  // roi_score [300,21]
  else out[RR * NCLS + r * 4 + (c - NCLS)] = mean;         // roi_locs  [300,4]
}

// ---------------- launch ----------------
extern "C" void kernel_launch(void* const* d_in, const int* in_sizes, int n_in,
                              void* d_out, int out_size) {
  const float* h    = (const float*)d_in[0];
  const float* rois = (const float*)d_in[1];
  const int*   ridx = (const int*)d_in[2];
  const float* w1   = (const float*)d_in[3];
  const float* b1   = (const float*)d_in[4];
  const float* wc   = (const float*)d_in[5];
  const float* bc   = (const float*)d_in[6];
  const float* wl   = (const float*)d_in[7];
  const float* bl   = (const float*)d_in[8];
  float* out = (float*)d_out;

  const int PSMEM = (CHUNK * PSTR + 2 * STG_F) * 4;   // 98560 B dynamic
  cudaFuncSetAttribute(k_poolproj, cudaFuncAttributeMaxDynamicSharedMemorySize, PSMEM);

  k1_prep_trx_bias<<<K1_PREP + K1_TRX + K1_BIAS, 256>>>(h, w1, b1, wc, bc, wl, bl);
  k2_fold_sat1<<<K2_FOLD + K2_SAT1, 128>>>(0);
  k_sat2<<<dim3(SATN, NB, 2), 128>>>();
  k_poolproj<<<dim3(PQN, (RR + CHUNK - 1) / CHUNK), 128, PSMEM>>>(rois, ridx);
  k_reduce<<<(RR * COMB + 255) / 256, 256>>>(out);
}

// round 14
// speedup vs baseline: 1.0074x; 1.0074x over previous
#include <cuda_runtime.h>
#include <cstdint>

#define NB 2
#define CIN 1024
#define HH 50
#define WW 50
#define SPAT 2500
#define SATN 51
#define SATSP (SATN * SATN)
#define RR 300
#define PQN 49
#define NCLS 21
#define ROWS_CLS 1029
#define ROWS_TOT 1225
#define COMB 25

// ---------------- scratch (static device memory; no allocations) ----------------
__device__ float4 g_ht4[(size_t)NB * SPAT * (CIN / 4)];   // tf32(h) channel-last
__device__ float4 g_sat4[(size_t)NB * SATSP * (CIN / 4)]; // SAT
__device__ float4 g_A4[(size_t)ROWS_TOT * (CIN / 4)];     // tf32(wc‖wl)
__device__ float4 g_B4[(size_t)CIN * (CIN / 4)];          // tf32(w1)
__device__ float4 g_W4[(size_t)ROWS_TOT * (CIN / 4)];     // folded weights (tf32 values)
__device__ float  g_bias[ROWS_TOT];                       // folded bias
__device__ float  g_scr[(size_t)RR * COMB * PQN];         // per-(roi,c,pq) values

// fp32 -> tf32-rounded fp32
__device__ __forceinline__ float tf32r(float x) {
  unsigned u;
  asm("cvt.rna.tf32.f32 %0, %1;" : "=r"(u) : "f"(x));
  return __uint_as_float(u);
}
__device__ __forceinline__ float4 tf32r4(float4 v) {
  return make_float4(tf32r(v.x), tf32r(v.y), tf32r(v.z), tf32r(v.w));
}

// cp.async helpers
__device__ __forceinline__ void cpa16(void* smem, const void* gmem, int srcsz) {
  uint32_t s = (uint32_t)__cvta_generic_to_shared(smem);
  asm volatile("cp.async.cg.shared.global [%0], [%1], 16, %2;\n"
               :: "r"(s), "l"(gmem), "r"(srcsz));
}
#define CP_COMMIT() asm volatile("cp.async.commit_group;\n" ::: "memory")
#define CP_WAIT1()  asm volatile("cp.async.wait_group 1;\n" ::: "memory")

// ---------------- K1: prep ∪ transpose ∪ bias (independent; blockIdx dispatch) -----
#define K1_PREP   (ROWS_TOT + CIN)                 // 2249 blocks
#define K1_TRX    ((79) * (CIN / 32) * NB)         // 79*32*2 = 5056 blocks
#define K1_BIAS   ((ROWS_TOT * 32 + 255) / 256)    // 154 blocks
__global__ __launch_bounds__(256) void k1_prep_trx_bias(
    const float* __restrict__ h,
    const float* __restrict__ w1, const float* __restrict__ b1,
    const float* __restrict__ wc, const float* __restrict__ bc,
    const float* __restrict__ wl, const float* __restrict__ bl) {
  __shared__ float tile[32][33];
  int bid = blockIdx.x;
  int t = threadIdx.x;

  if (bid < K1_PREP) {               // ---- prep: tf32-round + concat weights
    int j = bid;
    if (j < ROWS_TOT) {
      const float4* src = (j < ROWS_CLS)
          ? (const float4*)(wc + (size_t)j * CIN)
          : (const float4*)(wl + (size_t)(j - ROWS_CLS) * CIN);
      g_A4[(size_t)j * 256 + t] = tf32r4(src[t]);
    } else {
      int r = j - ROWS_TOT;
      g_B4[(size_t)r * 256 + t] = tf32r4(((const float4*)(w1 + (size_t)r * CIN))[t]);
    }
  } else if (bid < K1_PREP + K1_TRX) { // ---- transpose h -> ht (tf32)
    int b = bid - K1_PREP;
    int sxb = b % 79; b /= 79;
    int c0b = b % (CIN / 32); int n = b / (CIN / 32);
    int s0 = sxb * 32, c0 = c0b * 32;
    int tx = t & 31, ty = t >> 5;
    float* ht = (float*)g_ht4;
#pragma unroll
    for (int i = 0; i < 32; i += 8) {
      int c = c0 + ty + i, s = s0 + tx;
      if (c < CIN && s < SPAT) tile[ty + i][tx] = h[((size_t)n * CIN + c) * SPAT + s];
    }
    __syncthreads();
#pragma unroll
    for (int i = 0; i < 32; i += 8) {
      int s = s0 + ty + i, c = c0 + tx;
      if (s < SPAT && c < CIN) ht[((size_t)n * SPAT + s) * CIN + c] = tf32r(tile[tx][ty + i]);
    }
  } else {                            // ---- folded bias
    int b = bid - K1_PREP - K1_TRX;
    int gw = (b * 256 + t) >> 5;
    int lane = t & 31;
    if (gw >= ROWS_TOT) return;
    const float* row = (gw < ROWS_CLS) ? (wc + (size_t)gw * CIN)
                                       : (wl + (size_t)(gw - ROWS_CLS) * CIN);
    float s = 0.f;
    for (int o = lane; o < CIN; o += 32) s += row[o] * b1[o];
#pragma unroll
    for (int off = 16; off; off >>= 1) s += __shfl_xor_sync(0xffffffffu, s, off);
    if (lane == 0) {
      float base = (gw < ROWS_CLS) ? bc[gw] : bl[gw - ROWS_CLS];
      g_bias[gw] = base + s;
    }
  }
}

// ---------------- K2: fold ∪ sat1 (both depend only on K1) ----------------
#define KT 16
#define NKT (CIN / KT)
#define APAD 20
#define BPAD 68
#define K2_FOLD (16 * 20)        // 320 blocks
#define K2_SAT1 (SATN * NB * 2)  // 204 blocks
__global__ __launch_bounds__(128) void k2_fold_sat1(int dummy) {
  __shared__ float As[3][64][APAD];
  __shared__ float Bs[3][KT][BPAD];
  int bid = blockIdx.x;
  int t = threadIdx.x;

  if (bid < K2_FOLD) {   // ---- fold GEMM
    int warp = t >> 5, lane = t & 31;
    int n0 = (bid % 16) * 64;
    int m0 = (bid / 16) * 64;
    int warpM = warp >> 1, warpN = warp & 1;
    int mb = warpM * 32, nb = warpN * 32;
    int lg = lane >> 2, lt = lane & 3;

    const float* A = (const float*)g_A4;
    const float* B = (const float*)g_B4;

    int a_row0 = t >> 2, a_kq0 = (t & 3) << 2;
    int a_row1 = (128 + t) >> 2, a_kq1 = ((128 + t) & 3) << 2;
    int gm0 = m0 + a_row0, gm1 = m0 + a_row1;
    int ok0 = (gm0 < ROWS_TOT) ? 16 : 0;
    int ok1 = (gm1 < ROWS_TOT) ? 16 : 0;
    const float* a_src0 = A + (size_t)(ok0 ? gm0 : 0) * CIN + a_kq0;
    const float* a_src1 = A + (size_t)(ok1 ? gm1 : 0) * CIN + a_kq1;

    float c0[2][4], c1[2][4], c2[2][4], c3[2][4];
#pragma unroll
    for (int i = 0; i < 2; i++)
#pragma unroll
      for (int j = 0; j < 4; j++) { c0[i][j] = c1[i][j] = c2[i][j] = c3[i][j] = 0.f; }

    auto load_tile = [&](int kt, int st) {
      int k0 = kt * KT;
      cpa16(&As[st][a_row0][a_kq0], a_src0 + k0, ok0);
      cpa16(&As[st][a_row1][a_kq1], a_src1 + k0, ok1);
#pragma unroll
      for (int i = 0; i < 2; i++) {
        int idx = i * 128 + t;
        int kr = idx >> 4;
        int nq = (idx & 15) << 2;
        cpa16(&Bs[st][kr][nq], B + (size_t)(k0 + kr) * CIN + n0 + nq, 16);
      }
    };

    load_tile(0, 0); CP_COMMIT();
    load_tile(1, 1); CP_COMMIT();

    for (int kt = 0; kt < NKT; kt++) {
      int st = kt % 3;
      CP_WAIT1();
      __syncthreads();
#pragma unroll
      for (int ks = 0; ks < 2; ks++) {
        int kc = ks << 3;
        uint32_t a[2][4];
#pragma unroll
        for (int ms = 0; ms < 2; ms++) {
          int row = mb + (ms << 4) + lg;
          a[ms][0] = __float_as_uint(As[st][row][kc + lt]);
          a[ms][1] = __float_as_uint(As[st][row + 8][kc + lt]);
          a[ms][2] = __float_as_uint(As[st][row][kc + 4 + lt]);
          a[ms][3] = __float_as_uint(As[st][row + 8][kc + 4 + lt]);
        }
        uint32_t b[4][2];
#pragma unroll
        for (int ns = 0; ns < 4; ns++) {
          int col = nb + (ns << 3) + lg;
          b[ns][0] = __float_as_uint(Bs[st][kc + lt][col]);
          b[ns][1] = __float_as_uint(Bs[st][kc + 4 + lt][col]);
        }
#pragma unroll
        for (int ms = 0; ms < 2; ms++)
#pragma unroll
          for (int ns = 0; ns < 4; ns++) {
            asm volatile(
              "mma.sync.aligned.m16n8k8.row.col.f32.tf32.tf32.f32 "
              "{%0,%1,%2,%3}, {%4,%5,%6,%7}, {%8,%9}, {%0,%1,%2,%3};"
              : "+f"(c0[ms][ns]), "+f"(c1[ms][ns]), "+f"(c2[ms][ns]), "+f"(c3[ms][ns])
              : "r"(a[ms][0]), "r"(a[ms][1]), "r"(a[ms][2]), "r"(a[ms][3]),
                "r"(b[ns][0]), "r"(b[ns][1]));
          }
      }
      if (kt + 2 < NKT) load_tile(kt + 2, (kt + 2) % 3);
      CP_COMMIT();
    }

    float* W = (float*)g_W4;
#pragma unroll
    for (int ms = 0; ms < 2; ms++) {
      int gr = m0 + mb + (ms << 4) + lg;
#pragma unroll
      for (int ns = 0; ns < 4; ns++) {
        int gc = n0 + nb + (ns << 3) + (lt << 1);
        if (gr < ROWS_TOT)
          *(float2*)(W + (size_t)gr * CIN + gc) =
              make_float2(tf32r(c0[ms][ns]), tf32r(c1[ms][ns]));
        if (gr + 8 < ROWS_TOT)
          *(float2*)(W + (size_t)(gr + 8) * CIN + gc) =
              make_float2(tf32r(c2[ms][ns]), tf32r(c3[ms][ns]));
      }
    }
  } else {              // ---- sat1: prefix along x (8-deep prefetch)
    int b = bid - K2_FOLD;
    int by = b % SATN; b /= SATN;
    int n = b & 1;
    int c4 = (b >> 1) * 128 + t;
    float4* satb = g_sat4 + (size_t)n * SATSP * 256;
    if (by == 0) {
      float4 z = make_float4(0.f, 0.f, 0.f, 0.f);
      for (int x = 0; x < SATN; x++) satb[(size_t)x * 256 + c4] = z;
      return;
    }
    int y = by - 1;
    const float4* src = g_ht4 + ((size_t)n * SPAT + y * WW) * 256 + c4;
    float4* dst = satb + (size_t)(by * SATN) * 256 + c4;
    float4 acc = make_float4(0.f, 0.f, 0.f, 0.f);
    dst[0] = acc;
    float4 buf[8];
#pragma unroll
    for (int i = 0; i < 8; i++) buf[i] = src[(size_t)i * 256];
    for (int x0 = 0; x0 < 48; x0 += 8) {
#pragma unroll
      for (int j = 0; j < 8; j++) {
        float4 v = buf[j];
        if (x0 + 8 + j < WW) buf[j] = src[(size_t)(x0 + 8 + j) * 256];
        acc.x += v.x; acc.y += v.y; acc.z += v.z; acc.w += v.w;
        dst[(size_t)(x0 + 1 + j) * 256] = acc;
      }
    }
#pragma unroll
    for (int j = 0; j < 2; j++) {
      float4 v = buf[j];
      acc.x += v.x; acc.y += v.y; acc.z += v.z; acc.w += v.w;
      dst[(size_t)(49 + j) * 256] = acc;
    }
  }
}

// ---------------- K3: sat2 (prefix along y, in place, 8-deep prefetch) --------------
__global__ __launch_bounds__(128) void k_sat2() {
  int x = blockIdx.x;
  int n = blockIdx.y;
  int c4 = blockIdx.z * 128 + threadIdx.x;
  float4* p = g_sat4 + ((size_t)n * SATSP + x) * 256 + c4;
  const size_t RS = (size_t)SATN * 256;
  float4 acc = make_float4(0.f, 0.f, 0.f, 0.f);
  float4 buf[8];
#pragma unroll
  for (int i = 0; i < 8; i++) buf[i] = p[(size_t)(1 + i) * RS];
  for (int y0 = 0; y0 < 48; y0 += 8) {
#pragma unroll
    for (int j = 0; j < 8; j++) {
      float4 v = buf[j];
      if (y0 + 9 + j <= 50) buf[j] = p[(size_t)(y0 + 9 + j) * RS];
      acc.x += v.x; acc.y += v.y; acc.z += v.z; acc.w += v.w;
      p[(size_t)(y0 + 1 + j) * RS] = acc;
    }
  }
#pragma unroll
  for (int j = 0; j < 2; j++) {
    float4 v = buf[j];
    acc.x += v.x; acc.y += v.y; acc.z += v.z; acc.w += v.w;
    p[(size_t)(49 + j) * RS] = acc;
  }
}

// ---------------- roi geometry: XLA semantics (byte-identical to passing rounds) ----
__device__ __forceinline__ void roi_geom(const float* __restrict__ rois, int r, int p, int q,
                                         int& hs, int& he, int& ws, int& we) {
  float x1 = rois[4 * r + 0], y1 = rois[4 * r + 1];
  float x2 = rois[4 * r + 2], y2 = rois[4 * r + 3];
  float sw = __fmul_rn(rintf(x1), 0.0625f);
  float sh = __fmul_rn(rintf(y1), 0.0625f);
  float ew = __fmul_rn(rintf(__fadd_rn(x2, 1.0f)), 0.0625f);
  float eh = __fmul_rn(rintf(__fadd_rn(y2, 1.0f)), 0.0625f);
  float rw = fmaxf(__fadd_rn(ew, -sw), 0.1f);
  float rh = fmaxf(__fadd_rn(eh, -sh), 0.1f);
  const float RSEV = 1.0f / 7.0f;   // XLA: /7 -> * fl(1/7)
  float bh = __fmul_rn(rh, RSEV);
  float bw = __fmul_rn(rw, RSEV);
  float fp = (float)p, fq = (float)q;
  hs = (int)fminf(fmaxf(floorf(__fadd_rn(__fmul_rn(fp, bh), sh)), 0.f), 50.f);
  he = (int)fminf(fmaxf(ceilf(__fadd_rn(__fmul_rn(__fadd_rn(fp, 1.f), bh), sh)), 0.f), 50.f);
  ws = (int)fminf(fmaxf(floorf(__fadd_rn(__fmul_rn(fq, bw), sw)), 0.f), 50.f);
  we = (int)fminf(fmaxf(ceilf(__fadd_rn(__fmul_rn(__fadd_rn(fq, 1.f), bw), sw)), 0.f), 50.f);
}

__device__ __forceinline__ int row_of(int c, int pq) {
  return (c < NCLS) ? (c * PQN + pq) : (ROWS_CLS + (c - NCLS) * PQN + pq);
}

// ---------------- K4: fused pool + projection (exact R12 version) ------------------
// grid (49 pq, 19 chunks of 16 rois), 128 threads. Dynamic smem: Ps[16][1028].
// Phase B: KT=64, register-double-buffered W tiles, one sync per k-iter.
#define CHUNK 16
#define PSTR 1028
__global__ __launch_bounds__(128) void k_poolproj(const float* __restrict__ rois,
                                                  const int* __restrict__ ridx) {
  extern __shared__ float Ps[];        // [CHUNK][PSTR]
  __shared__ float As2[2][32][68];
  __shared__ float biasS[32];
  __shared__ float maskS[CHUNK];
  int pq = blockIdx.x, g = blockIdx.y;
  int p = pq / 7, q = pq - p * 7;
  int t = threadIdx.x;
  int warp = t >> 5, lane = t & 31;
  int lg = lane >> 2, lt = lane & 3;

  if (t < 32) biasS[t] = (t < COMB) ? g_bias[row_of(t, pq)] : 0.f;

  // Phase A: pooled vectors into smem (plain LDG corners; high MLP)
  for (int rr = 0; rr < CHUNK; rr++) {
    int r = g * CHUNK + rr;
    if (r < RR) {
      int hs, he, ws, we;
      roi_geom(rois, r, p, q, hs, he, ws, we);
      int n = ridx[r];
      int cnt = (he - hs) * (we - ws);
      float rcp = (cnt > 0) ? __fdiv_rn(1.0f, (float)cnt) : 0.0f;
      const float4* sat = g_sat4 + (size_t)n * SATSP * 256;
#pragma unroll
      for (int sgm = 0; sgm < 2; sgm++) {
        int c4 = t + sgm * 128;
        float4 s11 = sat[(size_t)(he * SATN + we) * 256 + c4];
        float4 s01 = sat[(size_t)(hs * SATN + we) * 256 + c4];
        float4 s10 = sat[(size_t)(he * SATN + ws) * 256 + c4];
        float4 s00 = sat[(size_t)(hs * SATN + ws) * 256 + c4];
        float4 acc = make_float4(((s11.x - s01.x) - (s10.x - s00.x)) * rcp,
                                 ((s11.y - s01.y) - (s10.y - s00.y)) * rcp,
                                 ((s11.z - s01.z) - (s10.z - s00.z)) * rcp,
                                 ((s11.w - s01.w) - (s10.w - s00.w)) * rcp);
        *(float4*)&Ps[rr * PSTR + (c4 << 2)] = tf32r4(acc);
      }
      if (t == 0) maskS[rr] = (cnt > 0) ? 1.0f : 0.0f;
    } else {
      float4 z = make_float4(0.f, 0.f, 0.f, 0.f);
#pragma unroll
      for (int sgm = 0; sgm < 2; sgm++)
        *(float4*)&Ps[rr * PSTR + ((t + sgm * 128) << 2)] = z;
      if (t == 0) maskS[rr] = 0.f;
    }
  }

  // Phase B: S[m, roi] = W[row_of(m,pq), :] . P[roi, :]   (M=32, N=16, K=1024)
  int ms = warp >> 1, ns = warp & 1;
  float c0 = 0.f, c1 = 0.f, c2 = 0.f, c3 = 0.f;
  const float* W = (const float*)g_W4;

  int tr = t >> 4;               // 0..7
  int f4c = (t & 15) << 2;       // 0..60
  const float* wp[4];
  int wok[4];
#pragma unroll
  for (int i = 0; i < 4; i++) {
    int m = 8 * i + tr;
    wok[i] = (m < COMB);
    wp[i] = W + (size_t)row_of(wok[i] ? m : 0, pq) * CIN + f4c;
  }
  float4 wbuf[4];
#pragma unroll
  for (int i = 0; i < 4; i++)
    wbuf[i] = wok[i] ? *(const float4*)(wp[i]) : make_float4(0.f, 0.f, 0.f, 0.f);
#pragma unroll
  for (int i = 0; i < 4; i++) *(float4*)&As2[0][8 * i + tr][f4c] = wbuf[i];
  __syncthreads();   // covers Ps (phase A) + As2[0]

  for (int kt = 0; kt < 16; kt++) {
    if (kt < 15) {
      int koff = (kt + 1) << 6;
#pragma unroll
      for (int i = 0; i < 4; i++)
        wbuf[i] = wok[i] ? *(const float4*)(wp[i] + koff) : make_float4(0.f, 0.f, 0.f, 0.f);
    }
    int bufc = kt & 1;
    int kbase = kt << 6;
#pragma unroll
    for (int ks = 0; ks < 8; ks++) {
      int kc = ks << 3;
      int row = (ms << 4) + lg;
      uint32_t a0 = __float_as_uint(As2[bufc][row][kc + lt]);
      uint32_t a1 = __float_as_uint(As2[bufc][row + 8][kc + lt]);
      uint32_t a2 = __float_as_uint(As2[bufc][row][kc + 4 + lt]);
      uint32_t a3 = __float_as_uint(As2[bufc][row + 8][kc + 4 + lt]);
      int col = (ns << 3) + lg;
      uint32_t b0 = __float_as_uint(Ps[col * PSTR + kbase + kc + lt]);
      uint32_t b1 = __float_as_uint(Ps[col * PSTR + kbase + kc + 4 + lt]);
      asm volatile(
        "mma.sync.aligned.m16n8k8.row.col.f32.tf32.tf32.f32 "
        "{%0,%1,%2,%3}, {%4,%5,%6,%7}, {%8,%9}, {%0,%1,%2,%3};"
        : "+f"(c0), "+f"(c1), "+f"(c2), "+f"(c3)
        : "r"(a0), "r"(a1), "r"(a2), "r"(a3), "r"(b0), "r"(b1));
    }
    if (kt < 15) {
#pragma unroll
      for (int i = 0; i < 4; i++) *(float4*)&As2[1 - bufc][8 * i + tr][f4c] = wbuf[i];
      __syncthreads();
    }
  }

  // epilogue
  int m_lo = (ms << 4) + lg, m_hi = m_lo + 8;
  int col0 = (ns << 3) + (lt << 1);
  float b_lo = biasS[m_lo], b_hi = biasS[m_hi];
#pragma unroll
  for (int rr2 = 0; rr2 < 2; rr2++) {
    int col = col0 + rr2;
    int r = g * CHUNK + col;
    if (r < RR) {
      float mk = maskS[col];
      if (m_lo < COMB)
        g_scr[((size_t)r * COMB + m_lo) * PQN + pq] = ((rr2 ? c1 : c0) + b_lo) * mk;
      if (m_hi < COMB)
        g_scr[((size_t)r * COMB + m_hi) * PQN + pq] = ((rr2 ? c3 : c2) + b_hi) * mk;
    }
  }
}

// ---------------- K5: reduce: mean over 49 bins = sum * fl(1/49) ----------------
__global__ void k_reduce(float* __restrict__ out) {
  int idx = blockIdx.x * blockDim.x + threadIdx.x;
  if (idx >= RR * COMB) return;
  int r = idx / COMB, c = idx - r * COMB;
  const float* src = g_scr + (size_t)idx * PQN;
  float s = 0.f;
#pragma unroll
  for (int pq = 0; pq < PQN; pq++) s += src[pq];
  float mean = __fmul_rn(s, 1.0f / 49.0f);
  if (c < NCLS) out[r * NCLS + c] = mean;                  // roi_score [300,21]
  else out[RR * NCLS + r * 4 + (c - NCLS)] = mean;         // roi_locs  [300,4]
}

// ---------------- launch ----------------
extern "C" void kernel_launch(void* const* d_in, const int* in_sizes, int n_in,
                              void* d_out, int out_size) {
  const float* h    = (const float*)d_in[0];
  const float* rois = (const float*)d_in[1];
  const int*   ridx = (const int*)d_in[2];
  const float* w1   = (const float*)d_in[3];
  const float* b1   = (const float*)d_in[4];
  const float* wc   = (const float*)d_in[5];
  const float* bc   = (const float*)d_in[6];
  const float* wl   = (const float*)d_in[7];
  const float* bl   = (const float*)d_in[8];
  float* out = (float*)d_out;

  const int PSMEM = CHUNK * PSTR * 4;   // 65792 B dynamic
  cudaFuncSetAttribute(k_poolproj, cudaFuncAttributeMaxDynamicSharedMemorySize, PSMEM);

  k1_prep_trx_bias<<<K1_PREP + K1_TRX + K1_BIAS, 256>>>(h, w1, b1, wc, bc, wl, bl);
  k2_fold_sat1<<<K2_FOLD + K2_SAT1, 128>>>(0);
  k_sat2<<<dim3(SATN, NB, 2), 128>>>();
  k_poolproj<<<dim3(PQN, (RR + CHUNK - 1) / CHUNK), 128, PSMEM>>>(rois, ridx);
  k_reduce<<<(RR * COMB + 255) / 256, 256>>>(out);
}

// round 15
// speedup vs baseline: 1.4762x; 1.4654x over previous
#include <cuda_runtime.h>
#include <cstdint>

#define NB 2
#define CIN 1024
#define HH 50
#define WW 50
#define SPAT 2500
#define SATN 51
#define SATSP (SATN * SATN)
#define RR 300
#define PQN 49
#define NCLS 21
#define ROWS_CLS 1029
#define ROWS_TOT 1225
#define COMB 25

// ---------------- scratch (static device memory; no allocations) ----------------
__device__ float4 g_sat4[(size_t)NB * SATSP * (CIN / 4)]; // SAT
__device__ float4 g_A4[(size_t)ROWS_TOT * (CIN / 4)];     // tf32(wc‖wl)
__device__ float4 g_B4[(size_t)CIN * (CIN / 4)];          // tf32(w1)
__device__ float4 g_W4[(size_t)ROWS_TOT * (CIN / 4)];     // folded weights (tf32 values)
__device__ float  g_bias[ROWS_TOT];                       // folded bias
__device__ float  g_scr[(size_t)RR * COMB * PQN];         // per-(roi,c,pq) values

// fp32 -> tf32-rounded fp32
__device__ __forceinline__ float tf32r(float x) {
  unsigned u;
  asm("cvt.rna.tf32.f32 %0, %1;" : "=r"(u) : "f"(x));
  return __uint_as_float(u);
}
__device__ __forceinline__ float4 tf32r4(float4 v) {
  return make_float4(tf32r(v.x), tf32r(v.y), tf32r(v.z), tf32r(v.w));
}

// cp.async helpers
__device__ __forceinline__ void cpa16(void* smem, const void* gmem, int srcsz) {
  uint32_t s = (uint32_t)__cvta_generic_to_shared(smem);
  asm volatile("cp.async.cg.shared.global [%0], [%1], 16, %2;\n"
               :: "r"(s), "l"(gmem), "r"(srcsz));
}
#define CP_COMMIT() asm volatile("cp.async.commit_group;\n" ::: "memory")
#define CP_WAIT1()  asm volatile("cp.async.wait_group 1;\n" ::: "memory")

// ---------------- 0. prep: tf32-round + concat weights (R12 exact) ----------------
__global__ void k_prep(const float* __restrict__ wc, const float* __restrict__ wl,
                       const float* __restrict__ w1) {
  int j = blockIdx.x;
  int t = threadIdx.x;
  if (j < ROWS_TOT) {
    const float4* src = (j < ROWS_CLS)
        ? (const float4*)(wc + (size_t)j * CIN)
        : (const float4*)(wl + (size_t)(j - ROWS_CLS) * CIN);
    g_A4[(size_t)j * 256 + t] = tf32r4(src[t]);
  } else {
    int r = j - ROWS_TOT;
    g_B4[(size_t)r * 256 + t] = tf32r4(((const float4*)(w1 + (size_t)r * CIN))[t]);
  }
}

// ---------------- 1. fused transpose + SAT pass 1 ----------------
// grid (51, NB, 8), 128 threads; channel slice c0 = z*128, one channel per thread.
// Reads h[n,c, y*50+x] via coalesced smem staging, prefix along x in identical
// serial order as before -> bit-identical SAT rows.
__global__ __launch_bounds__(128) void k_trxsat1(const float* __restrict__ h) {
  __shared__ float tile[128][51];   // [c_local][x], 51 stride = conflict-free
  int by = blockIdx.x, n = blockIdx.y, zc = blockIdx.z;
  int t = threadIdx.x;
  int c0 = zc * 128;
  float* satb = (float*)g_sat4 + (size_t)n * SATSP * 1024;

  if (by == 0) {                    // zero row y=0
    for (int x = 0; x < SATN; x++)
      satb[(size_t)x * 1024 + c0 + t] = 0.f;
    return;
  }
  int y = by - 1;
  const float* hb = h + ((size_t)n * CIN + c0) * SPAT + y * WW;
  for (int idx = t; idx < 128 * WW; idx += 128) {
    int cl = idx / WW, x = idx - cl * WW;
    tile[cl][x] = tf32r(hb[(size_t)cl * SPAT + x]);
  }
  __syncthreads();

  float acc = 0.f;
  float* dst = satb + c0 + t;
  dst[(size_t)(by * SATN) * 1024] = 0.f;          // x=0 column
#pragma unroll 10
  for (int x = 0; x < WW; x++) {
    acc += tile[t][x];
    dst[(size_t)(by * SATN + x + 1) * 1024] = acc;
  }
}

// ---------------- 2. SAT pass 2: prefix along y, in place (R12 exact) ---------------
__global__ __launch_bounds__(128) void k_sat2() {
  int x = blockIdx.x;
  int n = blockIdx.y;
  int c4 = blockIdx.z * 128 + threadIdx.x;
  float4* p = g_sat4 + ((size_t)n * SATSP + x) * 256 + c4;
  const size_t RS = (size_t)SATN * 256;
  float4 acc = make_float4(0.f, 0.f, 0.f, 0.f);
  float4 buf[8];
#pragma unroll
  for (int i = 0; i < 8; i++) buf[i] = p[(size_t)(1 + i) * RS];
  for (int y0 = 0; y0 < 48; y0 += 8) {
#pragma unroll
    for (int j = 0; j < 8; j++) {
      float4 v = buf[j];
      if (y0 + 9 + j <= 50) buf[j] = p[(size_t)(y0 + 9 + j) * RS];
      acc.x += v.x; acc.y += v.y; acc.z += v.z; acc.w += v.w;
      p[(size_t)(y0 + 1 + j) * RS] = acc;
    }
  }
#pragma unroll
  for (int j = 0; j < 2; j++) {     // y = 49, 50
    float4 v = buf[j];
    acc.x += v.x; acc.y += v.y; acc.z += v.z; acc.w += v.w;
    p[(size_t)(49 + j) * RS] = acc;
  }
}

// ---------------- 3. fold GEMM: tf32 mma, cp.async 3-stage, 64x64 (R12 exact) -------
#define KT 16
#define NKT (CIN / KT)
#define APAD 20
#define BPAD 68
__global__ __launch_bounds__(128) void k_fold_mma(int dummy) {
  __shared__ float As[3][64][APAD];
  __shared__ float Bs[3][KT][BPAD];
  int t = threadIdx.x;
  int warp = t >> 5, lane = t & 31;
  int n0 = blockIdx.x * 64;
  int m0 = blockIdx.y * 64;
  int warpM = warp >> 1, warpN = warp & 1;
  int mb = warpM * 32, nb = warpN * 32;
  int lg = lane >> 2, lt = lane & 3;

  const float* A = (const float*)g_A4;
  const float* B = (const float*)g_B4;

  int a_row0 = t >> 2, a_kq0 = (t & 3) << 2;
  int a_row1 = (128 + t) >> 2, a_kq1 = ((128 + t) & 3) << 2;
  int gm0 = m0 + a_row0, gm1 = m0 + a_row1;
  int ok0 = (gm0 < ROWS_TOT) ? 16 : 0;
  int ok1 = (gm1 < ROWS_TOT) ? 16 : 0;
  const float* a_src0 = A + (size_t)(ok0 ? gm0 : 0) * CIN + a_kq0;
  const float* a_src1 = A + (size_t)(ok1 ? gm1 : 0) * CIN + a_kq1;

  float c0[2][4], c1[2][4], c2[2][4], c3[2][4];
#pragma unroll
  for (int i = 0; i < 2; i++)
#pragma unroll
    for (int j = 0; j < 4; j++) { c0[i][j] = c1[i][j] = c2[i][j] = c3[i][j] = 0.f; }

  auto load_tile = [&](int kt, int st) {
    int k0 = kt * KT;
    cpa16(&As[st][a_row0][a_kq0], a_src0 + k0, ok0);
    cpa16(&As[st][a_row1][a_kq1], a_src1 + k0, ok1);
#pragma unroll
    for (int i = 0; i < 2; i++) {
      int idx = i * 128 + t;
      int kr = idx >> 4;
      int nq = (idx & 15) << 2;
      cpa16(&Bs[st][kr][nq], B + (size_t)(k0 + kr) * CIN + n0 + nq, 16);
    }
  };

  load_tile(0, 0); CP_COMMIT();
  load_tile(1, 1); CP_COMMIT();

  for (int kt = 0; kt < NKT; kt++) {
    int st = kt % 3;
    CP_WAIT1();
    __syncthreads();
#pragma unroll
    for (int ks = 0; ks < 2; ks++) {
      int kc = ks << 3;
      uint32_t a[2][4];
#pragma unroll
      for (int ms = 0; ms < 2; ms++) {
        int row = mb + (ms << 4) + lg;
        a[ms][0] = __float_as_uint(As[st][row][kc + lt]);
        a[ms][1] = __float_as_uint(As[st][row + 8][kc + lt]);
        a[ms][2] = __float_as_uint(As[st][row][kc + 4 + lt]);
        a[ms][3] = __float_as_uint(As[st][row + 8][kc + 4 + lt]);
      }
      uint32_t b[4][2];
#pragma unroll
      for (int ns = 0; ns < 4; ns++) {
        int col = nb + (ns << 3) + lg;
        b[ns][0] = __float_as_uint(Bs[st][kc + lt][col]);
        b[ns][1] = __float_as_uint(Bs[st][kc + 4 + lt][col]);
      }
#pragma unroll
      for (int ms = 0; ms < 2; ms++)
#pragma unroll
        for (int ns = 0; ns < 4; ns++) {
          asm volatile(
            "mma.sync.aligned.m16n8k8.row.col.f32.tf32.tf32.f32 "
            "{%0,%1,%2,%3}, {%4,%5,%6,%7}, {%8,%9}, {%0,%1,%2,%3};"
            : "+f"(c0[ms][ns]), "+f"(c1[ms][ns]), "+f"(c2[ms][ns]), "+f"(c3[ms][ns])
            : "r"(a[ms][0]), "r"(a[ms][1]), "r"(a[ms][2]), "r"(a[ms][3]),
              "r"(b[ns][0]), "r"(b[ns][1]));
        }
    }
    if (kt + 2 < NKT) load_tile(kt + 2, (kt + 2) % 3);
    CP_COMMIT();
  }

  float* W = (float*)g_W4;
#pragma unroll
  for (int ms = 0; ms < 2; ms++) {
    int gr = m0 + mb + (ms << 4) + lg;
#pragma unroll
    for (int ns = 0; ns < 4; ns++) {
      int gc = n0 + nb + (ns << 3) + (lt << 1);
      if (gr < ROWS_TOT)
        *(float2*)(W + (size_t)gr * CIN + gc) =
            make_float2(tf32r(c0[ms][ns]), tf32r(c1[ms][ns]));
      if (gr + 8 < ROWS_TOT)
        *(float2*)(W + (size_t)(gr + 8) * CIN + gc) =
            make_float2(tf32r(c2[ms][ns]), tf32r(c3[ms][ns]));
    }
  }
}

// ---------------- 4. folded bias (R12 exact) ----------------
__global__ void k_bias(const float* __restrict__ wc, const float* __restrict__ wl,
                       const float* __restrict__ bc, const float* __restrict__ bl,
                       const float* __restrict__ b1) {
  int gw = (blockIdx.x * blockDim.x + threadIdx.x) >> 5;
  int lane = threadIdx.x & 31;
  if (gw >= ROWS_TOT) return;
  const float* row = (gw < ROWS_CLS) ? (wc + (size_t)gw * CIN)
                                     : (wl + (size_t)(gw - ROWS_CLS) * CIN);
  float s = 0.f;
  for (int o = lane; o < CIN; o += 32) s += row[o] * b1[o];
#pragma unroll
  for (int off = 16; off; off >>= 1) s += __shfl_xor_sync(0xffffffffu, s, off);
  if (lane == 0) {
    float base = (gw < ROWS_CLS) ? bc[gw] : bl[gw - ROWS_CLS];
    g_bias[gw] = base + s;
  }
}

// ---------------- roi geometry: XLA semantics (byte-identical to passing rounds) ----
__device__ __forceinline__ void roi_geom(const float* __restrict__ rois, int r, int p, int q,
                                         int& hs, int& he, int& ws, int& we) {
  float x1 = rois[4 * r + 0], y1 = rois[4 * r + 1];
  float x2 = rois[4 * r + 2], y2 = rois[4 * r + 3];
  float sw = __fmul_rn(rintf(x1), 0.0625f);
  float sh = __fmul_rn(rintf(y1), 0.0625f);
  float ew = __fmul_rn(rintf(__fadd_rn(x2, 1.0f)), 0.0625f);
  float eh = __fmul_rn(rintf(__fadd_rn(y2, 1.0f)), 0.0625f);
  float rw = fmaxf(__fadd_rn(ew, -sw), 0.1f);
  float rh = fmaxf(__fadd_rn(eh, -sh), 0.1f);
  const float RSEV = 1.0f / 7.0f;   // XLA: /7 -> * fl(1/7)
  float bh = __fmul_rn(rh, RSEV);
  float bw = __fmul_rn(rw, RSEV);
  float fp = (float)p, fq = (float)q;
  hs = (int)fminf(fmaxf(floorf(__fadd_rn(__fmul_rn(fp, bh), sh)), 0.f), 50.f);
  he = (int)fminf(fmaxf(ceilf(__fadd_rn(__fmul_rn(__fadd_rn(fp, 1.f), bh), sh)), 0.f), 50.f);
  ws = (int)fminf(fmaxf(floorf(__fadd_rn(__fmul_rn(fq, bw), sw)), 0.f), 50.f);
  we = (int)fminf(fmaxf(ceilf(__fadd_rn(__fmul_rn(__fadd_rn(fq, 1.f), bw), sw)), 0.f), 50.f);
}

__device__ __forceinline__ int row_of(int c, int pq) {
  return (c < NCLS) ? (c * PQN + pq) : (ROWS_CLS + (c - NCLS) * PQN + pq);
}

// ---------------- 5. fused pool + projection (R12 exact) ----------------
#define CHUNK 16
#define PSTR 1028
__global__ __launch_bounds__(128) void k_poolproj(const float* __restrict__ rois,
                                                  const int* __restrict__ ridx) {
  extern __shared__ float Ps[];        // [CHUNK][PSTR]
  __shared__ float As2[2][32][68];
  __shared__ float biasS[32];
  __shared__ float maskS[CHUNK];
  int pq = blockIdx.x, g = blockIdx.y;
  int p = pq / 7, q = pq - p * 7;
  int t = threadIdx.x;
  int warp = t >> 5, lane = t & 31;
  int lg = lane >> 2, lt = lane & 3;

  if (t < 32) biasS[t] = (t < COMB) ? g_bias[row_of(t, pq)] : 0.f;

  // Phase A: pooled vectors into smem (plain LDG corners; high MLP)
  for (int rr = 0; rr < CHUNK; rr++) {
    int r = g * CHUNK + rr;
    if (r < RR) {
      int hs, he, ws, we;
      roi_geom(rois, r, p, q, hs, he, ws, we);
      int n = ridx[r];
      int cnt = (he - hs) * (we - ws);
      float rcp = (cnt > 0) ? __fdiv_rn(1.0f, (float)cnt) : 0.0f;
      const float4* sat = g_sat4 + (size_t)n * SATSP * 256;
#pragma unroll
      for (int sgm = 0; sgm < 2; sgm++) {
        int c4 = t + sgm * 128;
        float4 s11 = sat[(size_t)(he * SATN + we) * 256 + c4];
        float4 s01 = sat[(size_t)(hs * SATN + we) * 256 + c4];
        float4 s10 = sat[(size_t)(he * SATN + ws) * 256 + c4];
        float4 s00 = sat[(size_t)(hs * SATN + ws) * 256 + c4];
        float4 acc = make_float4(((s11.x - s01.x) - (s10.x - s00.x)) * rcp,
                                 ((s11.y - s01.y) - (s10.y - s00.y)) * rcp,
                                 ((s11.z - s01.z) - (s10.z - s00.z)) * rcp,
                                 ((s11.w - s01.w) - (s10.w - s00.w)) * rcp);
        *(float4*)&Ps[rr * PSTR + (c4 << 2)] = tf32r4(acc);
      }
      if (t == 0) maskS[rr] = (cnt > 0) ? 1.0f : 0.0f;
    } else {
      float4 z = make_float4(0.f, 0.f, 0.f, 0.f);
#pragma unroll
      for (int sgm = 0; sgm < 2; sgm++)
        *(float4*)&Ps[rr * PSTR + ((t + sgm * 128) << 2)] = z;
      if (t == 0) maskS[rr] = 0.f;
    }
  }

  // Phase B: S[m, roi] = W[row_of(m,pq), :] . P[roi, :]
  int ms = warp >> 1, ns = warp & 1;
  float c0 = 0.f, c1 = 0.f, c2 = 0.f, c3 = 0.f;
  const float* W = (const float*)g_W4;

  int tr = t >> 4;
  int f4c = (t & 15) << 2;
  const float* wp[4];
  int wok[4];
#pragma unroll
  for (int i = 0; i < 4; i++) {
    int m = 8 * i + tr;
    wok[i] = (m < COMB);
    wp[i] = W + (size_t)row_of(wok[i] ? m : 0, pq) * CIN + f4c;
  }
  float4 wbuf[4];
#pragma unroll
  for (int i = 0; i < 4; i++)
    wbuf[i] = wok[i] ? *(const float4*)(wp[i]) : make_float4(0.f, 0.f, 0.f, 0.f);
#pragma unroll
  for (int i = 0; i < 4; i++) *(float4*)&As2[0][8 * i + tr][f4c] = wbuf[i];
  __syncthreads();

  for (int kt = 0; kt < 16; kt++) {
    if (kt < 15) {
      int koff = (kt + 1) << 6;
#pragma unroll
      for (int i = 0; i < 4; i++)
        wbuf[i] = wok[i] ? *(const float4*)(wp[i] + koff) : make_float4(0.f, 0.f, 0.f, 0.f);
    }
    int bufc = kt & 1;
    int kbase = kt << 6;
#pragma unroll
    for (int ks = 0; ks < 8; ks++) {
      int kc = ks << 3;
      int row = (ms << 4) + lg;
      uint32_t a0 = __float_as_uint(As2[bufc][row][kc + lt]);
      uint32_t a1 = __float_as_uint(As2[bufc][row + 8][kc + lt]);
      uint32_t a2 = __float_as_uint(As2[bufc][row][kc + 4 + lt]);
      uint32_t a3 = __float_as_uint(As2[bufc][row + 8][kc + 4 + lt]);
      int col = (ns << 3) + lg;
      uint32_t b0 = __float_as_uint(Ps[col * PSTR + kbase + kc + lt]);
      uint32_t b1 = __float_as_uint(Ps[col * PSTR + kbase + kc + 4 + lt]);
      asm volatile(
        "mma.sync.aligned.m16n8k8.row.col.f32.tf32.tf32.f32 "
        "{%0,%1,%2,%3}, {%4,%5,%6,%7}, {%8,%9}, {%0,%1,%2,%3};"
        : "+f"(c0), "+f"(c1), "+f"(c2), "+f"(c3)
        : "r"(a0), "r"(a1), "r"(a2), "r"(a3), "r"(b0), "r"(b1));
    }
    if (kt < 15) {
#pragma unroll
      for (int i = 0; i < 4; i++) *(float4*)&As2[1 - bufc][8 * i + tr][f4c] = wbuf[i];
      __syncthreads();
    }
  }

  // epilogue
  int m_lo = (ms << 4) + lg, m_hi = m_lo + 8;
  int col0 = (ns << 3) + (lt << 1);
  float b_lo = biasS[m_lo], b_hi = biasS[m_hi];
#pragma unroll
  for (int rr2 = 0; rr2 < 2; rr2++) {
    int col = col0 + rr2;
    int r = g * CHUNK + col;
    if (r < RR) {
      float mk = maskS[col];
      if (m_lo < COMB)
        g_scr[((size_t)r * COMB + m_lo) * PQN + pq] = ((rr2 ? c1 : c0) + b_lo) * mk;
      if (m_hi < COMB)
        g_scr[((size_t)r * COMB + m_hi) * PQN + pq] = ((rr2 ? c3 : c2) + b_hi) * mk;
    }
  }
}

// ---------------- 6. reduce: mean over 49 bins = sum * fl(1/49) ----------------
__global__ void k_reduce(float* __restrict__ out) {
  int idx = blockIdx.x * blockDim.x + threadIdx.x;
  if (idx >= RR * COMB) return;
  int r = idx / COMB, c = idx - r * COMB;
  const float* src = g_scr + (size_t)idx * PQN;
  float s = 0.f;
#pragma unroll
  for (int pq = 0; pq < PQN; pq++) s += src[pq];
  float mean = __fmul_rn(s, 1.0f / 49.0f);
  if (c < NCLS) out[r * NCLS + c] = mean;                  // roi_score [300,21]
  else out[RR * NCLS + r * 4 + (c - NCLS)] = mean;         // roi_locs  [300,4]
}

// ---------------- launch ----------------
extern "C" void kernel_launch(void* const* d_in, const int* in_sizes, int n_in,
                              void* d_out, int out_size) {
  const float* h    = (const float*)d_in[0];
  const float* rois = (const float*)d_in[1];
  const int*   ridx = (const int*)d_in[2];
  const float* w1   = (const float*)d_in[3];
  const float* b1   = (const float*)d_in[4];
  const float* wc   = (const float*)d_in[5];
  const float* bc   = (const float*)d_in[6];
  const float* wl   = (const float*)d_in[7];
  const float* bl   = (const float*)d_in[8];
  float* out = (float*)d_out;

  const int PSMEM = CHUNK * PSTR * 4;   // 65792 B dynamic
  cudaFuncSetAttribute(k_poolproj, cudaFuncAttributeMaxDynamicSharedMemorySize, PSMEM);

  k_prep<<<ROWS_TOT + CIN, 256>>>(wc, wl, w1);
  k_trxsat1<<<dim3(SATN, NB, 8), 128>>>(h);
  k_fold_mma<<<dim3(CIN / 64, (ROWS_TOT + 63) / 64), 128>>>(0);
  k_sat2<<<dim3(SATN, NB, 2), 128>>>();
  k_bias<<<(ROWS_TOT * 32 + 255) / 256, 256>>>(bc ? wc : wc, wl, bc, bl, b1);
  k_poolproj<<<dim3(PQN, (RR + CHUNK - 1) / CHUNK), 128, PSMEM>>>(rois, ridx);
  k_reduce<<<(RR * COMB + 255) / 256, 256>>>(out);
}